// round 17
// baseline (speedup 1.0000x reference)
#include <cuda_runtime.h>
#include <math.h>
#include <stdint.h>

// Problem constants: B=8192 rows, H=4096 hidden, E=8 experts, TOP_K=2. fp32.
#define B_ROWS 8192
#define HDIM   4096
#define QSZ    1024         // H columns per gate block (quarter of H)
#define RPB    128          // rows per gate block
#define GSZ    8            // rows per pipeline group
#define NSLOT  3            // ring slots
#define NG     (RPB / GSZ)  // 16 groups

// Dynamic smem: 3 slots x 8 rows x 4KB + s_part + 3 full-mbarriers
#define SM_TILE_BYTES  (NSLOT * GSZ * 4096)            // 98304
#define SM_PART_OFF    SM_TILE_BYTES
#define SM_PART_BYTES  (2 * 8 * 8 * 9 * 4)             // 4608
#define SM_MBAR_OFF    (SM_PART_OFF + SM_PART_BYTES)   // 102912 (8-aligned)
#define SMEM_BYTES     (SM_MBAR_OFF + NSLOT * 8)

// Partial gate scores: g_part[row*32 + quarter*8 + e]
__device__ float g_part[(size_t)B_ROWS * 32];

// Packed f32x2 helpers (sm_10x packed fp32 pipe, PTX-only)
#define FMA2(d, a, b, c) asm("fma.rn.f32x2 %0, %1, %2, %3;" : "=l"(d) : "l"(a), "l"(b), "l"(c))
#define ADD2(d, a, b)    asm("add.rn.f32x2 %0, %1, %2;"     : "=l"(d) : "l"(a), "l"(b))
#define PACK2(d, x)      asm("mov.b64 %0, {%1, %1};"        : "=l"(d) : "r"(x))
#define UNPK2(lo, hi, s) asm("mov.b64 {%0, %1}, %2;"        : "=r"(lo), "=r"(hi) : "l"(s))

// mbarrier / bulk-copy PTX
#define MBAR_INIT(a, n) \
    asm volatile("mbarrier.init.shared.b64 [%0], %1;" :: "r"(a), "r"(n) : "memory")
#define MBAR_EXPECT_TX(a, n) \
    asm volatile("mbarrier.arrive.expect_tx.shared.b64 _, [%0], %1;" :: "r"(a), "r"(n) : "memory")
#define MBAR_WAIT(a, par) do {                                                   \
    asm volatile(                                                                \
        "{\n\t.reg .pred P1;\n\t"                                                \
        "WL_%=:\n\t"                                                             \
        "mbarrier.try_wait.parity.acquire.cta.shared::cta.b64 P1, [%0], %1, 0x989680;\n\t" \
        "@P1 bra.uni WD_%=;\n\t"                                                 \
        "bra.uni WL_%=;\n\t"                                                     \
        "WD_%=:\n\t}"                                                            \
        :: "r"(a), "r"(par) : "memory");                                         \
} while (0)
#define BULK_G2S(dst, src, bytes, mbar) \
    asm volatile("cp.async.bulk.shared::cta.global.mbarrier::complete_tx::bytes " \
                 "[%0], [%1], %2, [%3];" \
                 :: "r"(dst), "l"(src), "r"(bytes), "r"(mbar) : "memory")

static __device__ __forceinline__ uint32_t smem_u32(const void* p) {
    uint32_t a;
    asm("{ .reg .u64 t; cvta.to.shared.u64 t, %1; cvt.u32.u64 %0, t; }" : "=r"(a) : "l"(p));
    return a;
}

// ---------------------------------------------------------------------------
// Kernel 1: gate partials. grid = 256 blocks x 256 threads, 2 BLOCKS PER SM.
//
// KEY CHANGE vs R16: occupancy-2. All prior gate variants ran one 512-thread
// block per SM, so the block's own serial phases (mbar wait, barriers,
// stage-2) sat exposed on the critical path — hand-pipelining never fully
// hid them. With 256-thread blocks at 2/SM, the register budget is
// 64K/512 = 128 regs/thread (weights stay in registers, no spills — the trap
// that killed the 1024-thread variants at 64 regs), and the SIBLING block's
// compute/DRAM naturally overlaps this block's stalls.
//
// Decomposition: block (rg*4 + q) owns rows [rg*128, +128) and the H-quarter
// [q*1024, +1024). Thread t owns h = q*1024 + 4t..+3 -> 16 packed f32x2
// weight regs, loaded once. Ring: 3 slots x 8 rows x 4KB; thread 0 issues
// cp.async.bulk refill for group g+3 right after the consumption barrier.
// Per group: 8 LDS.128, barrier, refill, 2 FMA sub-batches of 4 rows +
// level-0/1 packed shfl compress, 8 interleaved tree finishes, s_part
// (double-buffered), barrier, stage-2 (64 (row,e) reductions over 8 warps)
// -> g_part[row*32 + q*8 + e]. Top-2 + softmax live in the combine kernel.
// ---------------------------------------------------------------------------
__global__ __launch_bounds__(256, 2) void gate_kernel(
    const float* __restrict__ hidden,
    const float* __restrict__ gw)     // (H, E) row-major
{
    extern __shared__ __align__(16) unsigned char dynsmem[];
    float* s_tile = reinterpret_cast<float*>(dynsmem);               // [24][1024]
    float* s_part = reinterpret_cast<float*>(dynsmem + SM_PART_OFF); // [2][8][8][9]

    const int t  = threadIdx.x;
    const int q  = (int)blockIdx.x & 3;
    const int base_row = ((int)blockIdx.x >> 2) * RPB;

    const uint32_t mb    = smem_u32(dynsmem + SM_MBAR_OFF);  // full[0..2]
    const uint32_t tile0 = smem_u32(dynsmem);
    const char* src = reinterpret_cast<const char*>(
        hidden + (size_t)base_row * HDIM + (size_t)q * QSZ);

    if (t == 0) {
#pragma unroll
        for (int s = 0; s < NSLOT; s++) MBAR_INIT(mb + s * 8, 1);
        asm volatile("fence.proxy.async.shared::cta;" ::: "memory");
    }
    __syncthreads();

    // Prologue: thread 0 issues groups 0..2 (slots 0..2).
    if (t == 0) {
#pragma unroll
        for (int g0 = 0; g0 < NSLOT; g0++) {
            MBAR_EXPECT_TX(mb + g0 * 8, GSZ * 4096);
#pragma unroll
            for (int i = 0; i < GSZ; i++)
                BULK_G2S(tile0 + (g0 * GSZ + i) * 4096,
                         src + (size_t)(g0 * GSZ + i) * (HDIM * 4), 4096,
                         mb + g0 * 8);
        }
    }

    const int lane = t & 31;
    const int wid  = t >> 5;   // 0..7
    // expert index held by this lane after the distribute-reduce: bitrev3(lane)
    const int e_lane = ((lane & 1) << 2) | (lane & 2) | ((lane >> 2) & 1);

    // 32 contiguous gate weights for this thread's 4 h positions -> 16 f32x2.
    long long g2[16];
    {
        const long long* gwp =
            reinterpret_cast<const long long*>(gw) + ((size_t)q * 256 + t) * 16;
#pragma unroll
        for (int i = 0; i < 16; i++) g2[i] = gwp[i];
    }

    for (int g = 0; g < NG; g++) {
        const int slot = g % NSLOT;
        const int par  = (g / NSLOT) & 1;
        const int buf  = g & 1;

        MBAR_WAIT(mb + slot * 8, par);

        // Pull all 8 rows (1 float4 each) into registers.
        float4 v[GSZ];
#pragma unroll
        for (int i = 0; i < GSZ; i++)
            v[i] = *reinterpret_cast<const float4*>(
                &s_tile[(slot * GSZ + i) * 1024 + t * 4]);

        __syncthreads();   // slot fully consumed

        // Refill this slot for group g+3 (overlaps all compute below + the
        // sibling block hides whatever this doesn't).
        if (t == 0 && g + NSLOT < NG) {
            MBAR_EXPECT_TX(mb + slot * 8, GSZ * 4096);
#pragma unroll
            for (int i = 0; i < GSZ; i++)
                BULK_G2S(tile0 + (slot * GSZ + i) * 4096,
                         src + (size_t)((g + NSLOT) * GSZ + i) * (HDIM * 4), 4096,
                         mb + slot * 8);
        }

        // 2 register-friendly FMA sub-batches of 4 rows; compress each row to
        // one packed reg (experts pair) via shfl levels 0-1.
        long long keep[GSZ];
#pragma unroll
        for (int sb = 0; sb < 2; sb++) {
            long long acc[4][4];
#pragma unroll
            for (int i = 0; i < 4; i++)
#pragma unroll
                for (int j = 0; j < 4; j++) acc[i][j] = 0;

#pragma unroll
            for (int k = 0; k < 4; k++) {
#pragma unroll
                for (int i = 0; i < 4; i++) {
                    const float4 vi = v[sb * 4 + i];
                    const float vk = (k == 0) ? vi.x : (k == 1) ? vi.y
                                   : (k == 2) ? vi.z : vi.w;
                    long long pv;
                    PACK2(pv, __float_as_int(vk));
                    FMA2(acc[i][0], pv, g2[k * 4 + 0], acc[i][0]);
                    FMA2(acc[i][1], pv, g2[k * 4 + 1], acc[i][1]);
                    FMA2(acc[i][2], pv, g2[k * 4 + 2], acc[i][2]);
                    FMA2(acc[i][3], pv, g2[k * 4 + 3], acc[i][3]);
                }
            }

#pragma unroll
            for (int i = 0; i < 4; i++) {
                long long a0 = acc[i][0], a1 = acc[i][1],
                          a2 = acc[i][2], a3 = acc[i][3];
                {   // level 0: xor 1
                    const bool hi = lane & 1;
                    long long s0 = hi ? a0 : a2;
                    long long s1 = hi ? a1 : a3;
                    long long q0 = __shfl_xor_sync(0xffffffffu, s0, 1);
                    long long q1 = __shfl_xor_sync(0xffffffffu, s1, 1);
                    long long k0 = hi ? a2 : a0;
                    long long k1 = hi ? a3 : a1;
                    ADD2(a0, k0, q0);
                    ADD2(a1, k1, q1);
                }
                {   // level 1: xor 2
                    const bool hi = lane & 2;
                    long long s0 = hi ? a0 : a1;
                    long long q0 = __shfl_xor_sync(0xffffffffu, s0, 2);
                    long long k0 = hi ? a1 : a0;
                    ADD2(a0, k0, q0);
                }
                keep[sb * 4 + i] = a0;
            }
        }

        // Tree finish for all 8 rows, interleaved (ILP-8).
        float val[GSZ];
#pragma unroll
        for (int i = 0; i < GSZ; i++) {
            int lo_i, hi_i;
            UNPK2(lo_i, hi_i, keep[i]);
            const float f0 = __int_as_float(lo_i);
            const float f1 = __int_as_float(hi_i);
            const bool hi = lane & 4;
            const float sv = hi ? f0 : f1;
            const float qq = __shfl_xor_sync(0xffffffffu, sv, 4);
            val[i] = (hi ? f1 : f0) + qq;
        }
#pragma unroll
        for (int i = 0; i < GSZ; i++)
            val[i] += __shfl_xor_sync(0xffffffffu, val[i], 8);
#pragma unroll
        for (int i = 0; i < GSZ; i++)
            val[i] += __shfl_xor_sync(0xffffffffu, val[i], 16);

        if (lane < 8) {
#pragma unroll
            for (int i = 0; i < GSZ; i++)
                s_part[((buf * GSZ + i) * 8 + wid) * 9 + e_lane] = val[i];
        }

        __syncthreads();   // s_part complete

        // stage 2: 64 (row,expert) reductions of 8 warp-partials, 8/warp.
        // s_part is parity-buffered; group g+2 rewrites this buf only after
        // its own first barrier, reached after this stage-2 -> race-free.
#pragma unroll
        for (int it = 0; it < 8; it++) {
            const int pid  = wid + it * 8;    // 0..63
            const int row8 = pid >> 3;
            const int e    = pid & 7;
            float p = (lane < 8)
                    ? s_part[((buf * GSZ + row8) * 8 + lane) * 9 + e] : 0.0f;
            p += __shfl_xor_sync(0xffffffffu, p, 4);
            p += __shfl_xor_sync(0xffffffffu, p, 2);
            p += __shfl_xor_sync(0xffffffffu, p, 1);
            if (lane == 0)
                g_part[(size_t)(base_row + g * GSZ + row8) * 32 + q * 8 + e] = p;
        }
    }
}

// ---------------------------------------------------------------------------
// Kernel 2: finalize top-2 + combine. One block per row (8192 x 256) — the
// proven DRAM-ceiling form (persistent variant regressed). Warp 0 preamble:
// score[e] = sum of 4 quarter partials + bias, shfl top-2 with smallest-index
// tie-break (matches lax.top_k), 2-way softmax (== softmax over 8 + top-2
// renorm). Then streaming combine: out[b,:] = p0*eo[i0,b,:] + p1*eo[i1,b,:],
// float4, 8 loads in flight, .cs hints (no reuse).
// ---------------------------------------------------------------------------
__global__ __launch_bounds__(256) void combine_kernel(
    const float* __restrict__ eo,
    const float* __restrict__ gb,
    float* __restrict__ out)
{
    const int b = (int)blockIdx.x;
    __shared__ float4 bc;

    if (threadIdx.x < 32) {
        const int lane = threadIdx.x;
        float s = -3.402823466e38f;
        if (lane < 8) {
            const float* gp = &g_part[(size_t)b * 32];
            s = ((gp[lane] + gp[8 + lane]) + (gp[16 + lane] + gp[24 + lane]))
                + gb[lane];
        }

        float v1 = s; int i1 = lane;
#pragma unroll
        for (int off = 4; off; off >>= 1) {
            const float ov = __shfl_xor_sync(0xffffffffu, v1, off);
            const int   oi = __shfl_xor_sync(0xffffffffu, i1, off);
            if (ov > v1 || (ov == v1 && oi < i1)) { v1 = ov; i1 = oi; }
        }
        float v2 = (lane == i1) ? -3.402823466e38f : s;
        int i2 = lane;
#pragma unroll
        for (int off = 4; off; off >>= 1) {
            const float ov = __shfl_xor_sync(0xffffffffu, v2, off);
            const int   oi = __shfl_xor_sync(0xffffffffu, i2, off);
            if (ov > v2 || (ov == v2 && oi < i2)) { v2 = ov; i2 = oi; }
        }
        if (lane == 0) {
            const float p1 = 1.0f / (1.0f + expf(v2 - v1));
            bc = make_float4(p1, 1.0f - p1, __int_as_float(i1), __int_as_float(i2));
        }
    }
    __syncthreads();

    const float4 rg = bc;
    const float p0 = rg.x, p1 = rg.y;
    const int i0 = __float_as_int(rg.z);
    const int i1 = __float_as_int(rg.w);

    const float4* e0 =
        reinterpret_cast<const float4*>(eo + ((size_t)i0 * B_ROWS + b) * HDIM);
    const float4* e1 =
        reinterpret_cast<const float4*>(eo + ((size_t)i1 * B_ROWS + b) * HDIM);
    float4* o = reinterpret_cast<float4*>(out + (size_t)b * HDIM);

    const int t = threadIdx.x;
    float4 a[4], c[4];
#pragma unroll
    for (int k = 0; k < 4; k++) {
        a[k] = __ldcs(&e0[t + k * 256]);
        c[k] = __ldcs(&e1[t + k * 256]);
    }
#pragma unroll
    for (int k = 0; k < 4; k++) {
        float4 r;
        r.x = p0 * a[k].x + p1 * c[k].x;
        r.y = p0 * a[k].y + p1 * c[k].y;
        r.z = p0 * a[k].z + p1 * c[k].z;
        r.w = p0 * a[k].w + p1 * c[k].w;
        __stcs(&o[t + k * 256], r);
    }
}

// ---------------------------------------------------------------------------
// Launch. Inputs (metadata order): hidden_states (B,H) f32, expert_outputs
// (E,B,H) f32, gate_w (H,E) f32, gate_b (E,) f32. Output: (B,H) f32.
// cudaFuncSetAttribute is a non-stream API (not captured) -> capture-safe.
// No allocs, no syncs.
// ---------------------------------------------------------------------------
extern "C" void kernel_launch(void* const* d_in, const int* in_sizes, int n_in,
                              void* d_out, int out_size)
{
    const float* hidden = (const float*)d_in[0];
    const float* eo     = (const float*)d_in[1];
    const float* gw     = (const float*)d_in[2];
    const float* gb     = (const float*)d_in[3];
    float* out = (float*)d_out;

    static bool attr_set = false;
    if (!attr_set) {
        cudaFuncSetAttribute(gate_kernel,
                             cudaFuncAttributeMaxDynamicSharedMemorySize,
                             SMEM_BYTES);
        attr_set = true;
    }

    gate_kernel<<<256, 256, SMEM_BYTES>>>(hidden, gw);
    combine_kernel<<<B_ROWS, 256>>>(eo, gb, out);
}